// round 1
// baseline (speedup 1.0000x reference)
#include <cuda_runtime.h>
#include <cuda_bf16.h>
#include <math.h>

// ForwardBackwardImputer: out[b,t,:] = x[b, idx_fwd[b,t], :]
// where mask[t] = all(|x[b,t,d]| <= 1e-6) and
// idx_fwd = inclusive cummax over t of (mask ? 0 : t).
// (The reference's backward-fill branch is provably identical to x_fwd for
//  all selected rows, since inclusive cummax forces idx_bwd==0 on masked rows.)

#define L_SEQ 2048
#define D_FEAT 128
#define NTHREADS 512
#define NWARPS 16
#define ROW_F4 (D_FEAT / 4)   // 32 float4 per row
#define ATOL_F 1e-6f

__global__ __launch_bounds__(NTHREADS, 2)
void fwd_fill_kernel(const float* __restrict__ x, float* __restrict__ out) {
    const int b = blockIdx.x;
    const float4* __restrict__ xb =
        reinterpret_cast<const float4*>(x + (size_t)b * L_SEQ * D_FEAT);
    float4* __restrict__ ob =
        reinterpret_cast<float4*>(out + (size_t)b * L_SEQ * D_FEAT);

    __shared__ unsigned char s_mask[L_SEQ];
    __shared__ short s_idx[L_SEQ];
    __shared__ int s_wtot[NWARPS];

    const int tid  = threadIdx.x;
    const int lane = tid & 31;
    const int wid  = tid >> 5;
    const unsigned FULL = 0xffffffffu;

    // ---------------- Phase 1: mask + copy-out valid rows ----------------
    // Warp w handles rows w, w+16, ... Each lane owns one float4 of the row.
    for (int t = wid; t < L_SEQ; t += NWARPS) {
        float4 v = xb[t * ROW_F4 + lane];
        bool z = (fabsf(v.x) <= ATOL_F) & (fabsf(v.y) <= ATOL_F) &
                 (fabsf(v.z) <= ATOL_F) & (fabsf(v.w) <= ATOL_F);
        unsigned all_zero = __all_sync(FULL, z);
        if (!all_zero) {
            ob[t * ROW_F4 + lane] = v;   // valid row: write straight through
        }
        if (lane == 0) s_mask[t] = (unsigned char)all_zero;
    }
    __syncthreads();

    // ---------------- Phase 2: block-wide inclusive max-scan --------------
    // Each thread handles 4 consecutive timesteps.
    const int t0 = tid << 2;
    int vloc[4];
    int run = 0;
    #pragma unroll
    for (int i = 0; i < 4; i++) {
        int t = t0 + i;
        int v = s_mask[t] ? 0 : t;
        if (v > run) run = v;
        vloc[i] = run;               // thread-local inclusive scan
    }

    // Warp-level inclusive max-scan of per-thread totals.
    int incl = run;
    #pragma unroll
    for (int o = 1; o < 32; o <<= 1) {
        int n = __shfl_up_sync(FULL, incl, o);
        if (lane >= o && n > incl) incl = n;
    }
    if (lane == 31) s_wtot[wid] = incl;
    int pre = __shfl_up_sync(FULL, incl, 1);
    int texcl = (lane == 0) ? 0 : pre;   // thread-exclusive prefix within warp
    __syncthreads();

    // Serial exclusive max-scan over 16 warp totals (trivial cost).
    if (tid == 0) {
        int r = 0;
        #pragma unroll
        for (int w = 0; w < NWARPS; w++) {
            int tmp = s_wtot[w];
            s_wtot[w] = r;
            if (tmp > r) r = tmp;
        }
    }
    __syncthreads();

    int base = s_wtot[wid];
    if (texcl > base) base = texcl;
    #pragma unroll
    for (int i = 0; i < 4; i++) {
        int v = vloc[i] > base ? vloc[i] : base;
        s_idx[t0 + i] = (short)v;
    }
    __syncthreads();

    // ---------------- Phase 3: fill masked rows via gather ----------------
    for (int t = wid; t < L_SEQ; t += NWARPS) {
        if (s_mask[t]) {
            int s = (int)s_idx[t];
            ob[t * ROW_F4 + lane] = xb[s * ROW_F4 + lane];
        }
    }
}

extern "C" void kernel_launch(void* const* d_in, const int* in_sizes, int n_in,
                              void* d_out, int out_size) {
    const float* x = (const float*)d_in[0];
    float* out = (float*)d_out;
    int B = in_sizes[0] / (L_SEQ * D_FEAT);
    fwd_fill_kernel<<<B, NTHREADS>>>(x, out);
}